// round 4
// baseline (speedup 1.0000x reference)
#include <cuda_runtime.h>
#include <cuda_fp16.h>

#define BATCH   64
#define NATOMS  64
#define HDIM    256
#define NROWS   (2 * BATCH * NATOMS)   /* 8192 */
#define H2      (HDIM / 2)             /* 128 half2 per row */

/* s = [h1@W1[:H]+b1 ; h2@W1[H:]] packed half2 (4 MB) */
__device__ unsigned g_sh[NROWS * H2];
__device__ float g_rp[BATCH * NATOMS * 2];   /* row partials, 2 j-halves */
__device__ float g_cp[BATCH * NATOMS * 2];   /* col partials, 2 i-halves */

__device__ __forceinline__ unsigned pack_h2(float x, float y) {
    __half2 h = __floats2half2_rn(x, y);
    return *reinterpret_cast<unsigned*>(&h);
}
__device__ __forceinline__ unsigned tanh2u(unsigned x) {
    unsigned y; asm("tanh.approx.f16x2 %0, %1;" : "=r"(y) : "r"(x)); return y;
}
__device__ __forceinline__ __half2 u2h(unsigned u) {
    return *reinterpret_cast<__half2*>(&u);
}
__device__ __forceinline__ unsigned hadd2u(unsigned a, unsigned b) {
    __half2 r = __hadd2(u2h(a), u2h(b));
    return *reinterpret_cast<unsigned*>(&r);
}
__device__ __forceinline__ void cp_async16(void* smem, const void* gmem) {
    unsigned s = (unsigned)__cvta_generic_to_shared(smem);
    asm volatile("cp.async.cg.shared.global [%0], [%1], 16;" :: "r"(s), "l"(gmem));
}

/* ===== tf32 tensor GEMM, 64x64 tile, 256 thr, 2-stage cp.async ===== */
__global__ void __launch_bounds__(256) gemm_kernel(
    const float* __restrict__ h1, const float* __restrict__ h2,
    const float* __restrict__ W1, const float* __restrict__ b1)
{
    __shared__ float As[2][64 * 36];   /* [row][k] pad 36: frag loads conflict-free */
    __shared__ float Bs[2][32 * 72];   /* [k][n]   pad 72: frag loads conflict-free */

    const int row0 = blockIdx.x * 64;
    const int n0   = blockIdx.y * 64;
    const bool second = (row0 >= BATCH * NATOMS);
    const float* A = second ? h2 + (row0 - BATCH * NATOMS) * HDIM
                            : h1 + row0 * HDIM;
    const float* W = W1 + (second ? HDIM * HDIM : 0);

    const int tid = threadIdx.x;
    const int lane = tid & 31, w = tid >> 5;
    const int wm = w >> 2, wn = w & 3;            /* 2x4 warp grid: m32 x n16 */
    const int gid = lane >> 2, tig = lane & 3;

    /* staging indices: 2 A-float4 + 2 B-float4 per thread */
    int ar[2], ac[2], bk[2], bn[2];
#pragma unroll
    for (int l = 0; l < 2; l++) {
        int f = tid + l * 256;
        ar[l] = f >> 3;  ac[l] = f & 7;
        bk[l] = f >> 4;  bn[l] = f & 15;
    }

    float acc[2][2][4];
#pragma unroll
    for (int mt = 0; mt < 2; mt++)
#pragma unroll
        for (int nt = 0; nt < 2; nt++)
#pragma unroll
            for (int q = 0; q < 4; q++) acc[mt][nt][q] = 0.f;

    /* prologue: stage k-chunk 0 */
#pragma unroll
    for (int l = 0; l < 2; l++)
        cp_async16(&As[0][ar[l] * 36 + ac[l] * 4], A + ar[l] * HDIM + ac[l] * 4);
#pragma unroll
    for (int l = 0; l < 2; l++)
        cp_async16(&Bs[0][bk[l] * 72 + bn[l] * 4], W + bk[l] * HDIM + n0 + bn[l] * 4);
    asm volatile("cp.async.commit_group;");

    for (int kci = 0; kci < 8; kci++) {
        const int s = kci & 1;
        if (kci + 1 < 8) {
            const int kc = (kci + 1) * 32;
#pragma unroll
            for (int l = 0; l < 2; l++)
                cp_async16(&As[s ^ 1][ar[l] * 36 + ac[l] * 4],
                           A + ar[l] * HDIM + kc + ac[l] * 4);
#pragma unroll
            for (int l = 0; l < 2; l++)
                cp_async16(&Bs[s ^ 1][bk[l] * 72 + bn[l] * 4],
                           W + (kc + bk[l]) * HDIM + n0 + bn[l] * 4);
            asm volatile("cp.async.commit_group;");
            asm volatile("cp.async.wait_group 1;");
        } else {
            asm volatile("cp.async.wait_group 0;");
        }
        __syncthreads();

        const unsigned* Au = (const unsigned*)As[s];
        const unsigned* Bu = (const unsigned*)Bs[s];
#pragma unroll
        for (int ks = 0; ks < 4; ks++) {
            unsigned a[2][4], bfr[2][2];
#pragma unroll
            for (int mt = 0; mt < 2; mt++) {
                int r = wm * 32 + mt * 16 + gid;
                int kk = ks * 8 + tig;
                a[mt][0] = Au[r * 36 + kk];
                a[mt][1] = Au[(r + 8) * 36 + kk];
                a[mt][2] = Au[r * 36 + kk + 4];
                a[mt][3] = Au[(r + 8) * 36 + kk + 4];
            }
#pragma unroll
            for (int nt = 0; nt < 2; nt++) {
                int c = wn * 16 + nt * 8 + gid;
                bfr[nt][0] = Bu[(ks * 8 + tig) * 72 + c];
                bfr[nt][1] = Bu[(ks * 8 + tig + 4) * 72 + c];
            }
#pragma unroll
            for (int mt = 0; mt < 2; mt++)
#pragma unroll
                for (int nt = 0; nt < 2; nt++)
                    asm volatile(
                        "mma.sync.aligned.m16n8k8.row.col.f32.tf32.tf32.f32 "
                        "{%0,%1,%2,%3}, {%4,%5,%6,%7}, {%8,%9}, {%0,%1,%2,%3};"
                        : "+f"(acc[mt][nt][0]), "+f"(acc[mt][nt][1]),
                          "+f"(acc[mt][nt][2]), "+f"(acc[mt][nt][3])
                        : "r"(a[mt][0]), "r"(a[mt][1]), "r"(a[mt][2]), "r"(a[mt][3]),
                          "r"(bfr[nt][0]), "r"(bfr[nt][1]));
        }
        __syncthreads();
    }

    /* epilogue: +b1 (first half only), pack half2, store */
#pragma unroll
    for (int mt = 0; mt < 2; mt++) {
        int r = row0 + wm * 32 + mt * 16 + gid;
#pragma unroll
        for (int nt = 0; nt < 2; nt++) {
            int col = n0 + wn * 16 + nt * 8 + tig * 2;
            float bx = 0.f, by = 0.f;
            if (!second) { float2 bv = *(const float2*)(b1 + col); bx = bv.x; by = bv.y; }
            g_sh[r * H2 + (col >> 1)]       = pack_h2(acc[mt][nt][0] + bx, acc[mt][nt][1] + by);
            g_sh[(r + 8) * H2 + (col >> 1)] = pack_h2(acc[mt][nt][2] + bx, acc[mt][nt][3] + by);
        }
    }
}

/* ===== fused score: tanh.f16x2 + packed f32x2 FMA accumulation ===== */
__global__ void __launch_bounds__(256) score_kernel(const float* __restrict__ W2)
{
    __shared__ unsigned s1s[32 * 128];           /* [i][hh] half2            */
    __shared__ unsigned s2s[32 * 129];           /* [j][hh] pad: conflict-free */
    __shared__ unsigned long long w2p[128];      /* packed f32x2 pairs       */
    __shared__ float colbuf[8][32];

    const int jh = blockIdx.x, ih = blockIdx.y, b = blockIdx.z;
    const int tid = threadIdx.x, lane = tid & 31, w = tid >> 5;

    if (tid < 128) {
        float2 v = *(const float2*)(W2 + tid * 2);
        unsigned long long p;
        asm("mov.b64 %0, {%1, %2};" : "=l"(p) : "f"(v.x), "f"(v.y));
        w2p[tid] = p;
    }

    /* s1: 32 rows x 128 half2 = 1024 uint4 (4/thread), linear */
    const unsigned* s1g = g_sh + (b * NATOMS + ih * 32) * H2;
#pragma unroll
    for (int l = 0; l < 4; l++) {
        int f = tid + l * 256;
        *(uint4*)&s1s[f * 4] = *(const uint4*)(s1g + f * 4);
    }
    /* s2: pad-129 rows, scalar stores */
    const unsigned* s2g = g_sh + (BATCH * NATOMS + b * NATOMS + jh * 32) * H2;
#pragma unroll
    for (int l = 0; l < 4; l++) {
        int f = tid + l * 256;
        int j = f >> 5, q = f & 31;
        uint4 v = *(const uint4*)(s2g + f * 4);
        unsigned* d = &s2s[j * 129 + q * 4];
        d[0] = v.x; d[1] = v.y; d[2] = v.z; d[3] = v.w;
    }
    __syncthreads();

    /* warp w owns i rows [w*4, w*4+4), lane = local j */
    const unsigned* s2row = &s2s[lane * 129];
    unsigned long long acc[4];
#pragma unroll
    for (int ii = 0; ii < 4; ii++) acc[ii] = 0ull;

#pragma unroll 4
    for (int hh = 0; hh < 128; hh++) {
        unsigned long long wp = w2p[hh];   /* LDS.64 broadcast */
        unsigned b2 = s2row[hh];           /* conflict-free    */
#pragma unroll
        for (int ii = 0; ii < 4; ii++) {
            unsigned a2 = s1s[(w * 4 + ii) * 128 + hh];   /* broadcast */
            unsigned t = tanh2u(hadd2u(a2, b2));
            float2 tf = __half22float2(u2h(t));
            unsigned long long tp;
            asm("mov.b64 %0, {%1, %2};" : "=l"(tp) : "f"(tf.x), "f"(tf.y));
            asm("fma.rn.f32x2 %0, %1, %2, %0;" : "+l"(acc[ii]) : "l"(wp), "l"(tp));
        }
    }

    float colacc = 0.f;
#pragma unroll
    for (int ii = 0; ii < 4; ii++) {
        float lo, hi;
        asm("mov.b64 {%0, %1}, %2;" : "=f"(lo), "=f"(hi) : "l"(acc[ii]));
        float e = __expf(lo + hi);         /* bounded scores: no max pass */
        colacc += e;
        float rs = e;
#pragma unroll
        for (int o = 16; o > 0; o >>= 1)
            rs += __shfl_xor_sync(0xffffffffu, rs, o);
        if (lane == 0)
            g_rp[(b * NATOMS + ih * 32 + w * 4 + ii) * 2 + jh] = rs;
    }
    colbuf[w][lane] = colacc;
    __syncthreads();
    if (tid < 32) {
        float s = 0.f;
#pragma unroll
        for (int ww = 0; ww < 8; ww++) s += colbuf[ww][tid];
        g_cp[(b * NATOMS + jh * 32 + tid) * 2 + ih] = s;
    }
}

/* ---------------- normalize ---------------- */
__global__ void __launch_bounds__(64) finalize_kernel(float* __restrict__ out)
{
    int b = blockIdx.x, i = threadIdx.x;
    float r = g_rp[(b * 64 + i) * 2] + g_rp[(b * 64 + i) * 2 + 1];
    float c = g_cp[(b * 64 + i) * 2] + g_cp[(b * 64 + i) * 2 + 1];
    __shared__ float red[64];
    red[i] = r;
    __syncthreads();
    if (i < 32) {
        float v = red[i] + red[i + 32];
#pragma unroll
        for (int o = 16; o > 0; o >>= 1)
            v += __shfl_xor_sync(0xffffffffu, v, o);
        if (i == 0) red[0] = v;
    }
    __syncthreads();
    float inv = 1.f / red[0];
    out[b * 64 + i] = r * inv;
    out[BATCH * NATOMS + b * 64 + i] = c * inv;
}

extern "C" void kernel_launch(void* const* d_in, const int* in_sizes, int n_in,
                              void* d_out, int out_size)
{
    const float *h1 = nullptr, *h2 = nullptr, *W1 = nullptr,
                *b1 = nullptr, *W2 = nullptr;
    for (int idx = 0; idx < n_in; idx++) {
        int sz = in_sizes[idx];
        if (sz == BATCH * NATOMS * HDIM) {
            if (!h1) h1 = (const float*)d_in[idx];
            else if (!h2) h2 = (const float*)d_in[idx];
        } else if (sz == 2 * HDIM * HDIM) {
            W1 = (const float*)d_in[idx];
        } else if (sz == HDIM) {
            if (!b1) b1 = (const float*)d_in[idx];
            else if (!W2) W2 = (const float*)d_in[idx];
        }
    }
    float* out = (float*)d_out;

    gemm_kernel<<<dim3(NROWS / 64, HDIM / 64), 256>>>(h1, h2, W1, b1);
    score_kernel<<<dim3(2, 2, BATCH), 256>>>(W2);
    finalize_kernel<<<BATCH, 64>>>(out);
}

// round 5
// speedup vs baseline: 1.0339x; 1.0339x over previous
#include <cuda_runtime.h>
#include <cuda_fp16.h>

#define BATCH   64
#define NATOMS  64
#define HDIM    256
#define NROWS   (2 * BATCH * NATOMS)   /* 8192 */
#define H2      (HDIM / 2)             /* 128 half2 per row */

/* s = [h1@W1[:H]+b1 ; h2@W1[H:]] packed half2 (4 MB) */
__device__ unsigned g_sh[NROWS * H2];
__device__ float g_rp[BATCH * NATOMS * 2];   /* row partials, 2 j-halves   */
__device__ float g_cp[BATCH * NATOMS * 4];   /* col partials, 4 i-quarters */

__device__ __forceinline__ unsigned pack_h2(float x, float y) {
    __half2 h = __floats2half2_rn(x, y);
    return *reinterpret_cast<unsigned*>(&h);
}
__device__ __forceinline__ unsigned tanh2u(unsigned x) {
    unsigned y; asm("tanh.approx.f16x2 %0, %1;" : "=r"(y) : "r"(x)); return y;
}
__device__ __forceinline__ __half2 u2h(unsigned u) {
    return *reinterpret_cast<__half2*>(&u);
}
__device__ __forceinline__ unsigned hadd2u(unsigned a, unsigned b) {
    __half2 r = __hadd2(u2h(a), u2h(b));
    return *reinterpret_cast<unsigned*>(&r);
}
__device__ __forceinline__ void cp_async16(void* smem, const void* gmem) {
    unsigned s = (unsigned)__cvta_generic_to_shared(smem);
    asm volatile("cp.async.cg.shared.global [%0], [%1], 16;" :: "r"(s), "l"(gmem));
}

/* ===== tf32 tensor GEMM, 64x64 tile, 128 thr, 3-stage cp.async ===== */
__global__ void __launch_bounds__(128) gemm_kernel(
    const float* __restrict__ h1, const float* __restrict__ h2,
    const float* __restrict__ W1, const float* __restrict__ b1)
{
    __shared__ float As[3][64 * 36];   /* [row][k] pad 36: conflict-free frags */
    __shared__ float Bs[3][32 * 72];   /* [k][n]   pad 72: conflict-free frags */

    const int row0 = blockIdx.x * 64;
    const int n0   = blockIdx.y * 64;
    const bool second = (row0 >= BATCH * NATOMS);
    const float* A = second ? h2 + (row0 - BATCH * NATOMS) * HDIM
                            : h1 + row0 * HDIM;
    const float* W = W1 + (second ? HDIM * HDIM : 0);

    const int tid = threadIdx.x;
    const int lane = tid & 31, w = tid >> 5;
    const int wm = w >> 1, wn = w & 1;            /* 2x2 warp grid over 64x64 */
    const int gid = lane >> 2, tig = lane & 3;

    int ar[4], ac[4], bk[4], bn[4];
#pragma unroll
    for (int l = 0; l < 4; l++) {
        int f = tid + l * 128;
        ar[l] = f >> 3;  ac[l] = f & 7;
        bk[l] = f >> 4;  bn[l] = f & 15;
    }

    float acc[2][4][4];
#pragma unroll
    for (int mt = 0; mt < 2; mt++)
#pragma unroll
        for (int nt = 0; nt < 4; nt++)
#pragma unroll
            for (int q = 0; q < 4; q++) acc[mt][nt][q] = 0.f;

    /* prologue: stage k-chunks 0 and 1 */
#pragma unroll
    for (int c = 0; c < 2; c++) {
        const int kc = c * 32;
#pragma unroll
        for (int l = 0; l < 4; l++)
            cp_async16(&As[c][ar[l] * 36 + ac[l] * 4],
                       A + ar[l] * HDIM + kc + ac[l] * 4);
#pragma unroll
        for (int l = 0; l < 4; l++)
            cp_async16(&Bs[c][bk[l] * 72 + bn[l] * 4],
                       W + (kc + bk[l]) * HDIM + n0 + bn[l] * 4);
        asm volatile("cp.async.commit_group;");
    }

    for (int kci = 0; kci < 8; kci++) {
        const int s = kci % 3;
        if (kci + 2 < 8) {
            const int kc = (kci + 2) * 32;
            const int sn = (kci + 2) % 3;
#pragma unroll
            for (int l = 0; l < 4; l++)
                cp_async16(&As[sn][ar[l] * 36 + ac[l] * 4],
                           A + ar[l] * HDIM + kc + ac[l] * 4);
#pragma unroll
            for (int l = 0; l < 4; l++)
                cp_async16(&Bs[sn][bk[l] * 72 + bn[l] * 4],
                           W + (kc + bk[l]) * HDIM + n0 + bn[l] * 4);
            asm volatile("cp.async.commit_group;");
            asm volatile("cp.async.wait_group 2;");
        } else if (kci == 6) {
            asm volatile("cp.async.wait_group 1;");
        } else {
            asm volatile("cp.async.wait_group 0;");
        }
        __syncthreads();

        const unsigned* Au = (const unsigned*)As[s];
        const unsigned* Bu = (const unsigned*)Bs[s];
#pragma unroll
        for (int ks = 0; ks < 4; ks++) {
            unsigned a[2][4], bfr[4][2];
#pragma unroll
            for (int mt = 0; mt < 2; mt++) {
                int r = wm * 32 + mt * 16 + gid;
                int kk = ks * 8 + tig;
                a[mt][0] = Au[r * 36 + kk];
                a[mt][1] = Au[(r + 8) * 36 + kk];
                a[mt][2] = Au[r * 36 + kk + 4];
                a[mt][3] = Au[(r + 8) * 36 + kk + 4];
            }
#pragma unroll
            for (int nt = 0; nt < 4; nt++) {
                int c = wn * 32 + nt * 8 + gid;
                bfr[nt][0] = Bu[(ks * 8 + tig) * 72 + c];
                bfr[nt][1] = Bu[(ks * 8 + tig + 4) * 72 + c];
            }
#pragma unroll
            for (int mt = 0; mt < 2; mt++)
#pragma unroll
                for (int nt = 0; nt < 4; nt++)
                    asm volatile(
                        "mma.sync.aligned.m16n8k8.row.col.f32.tf32.tf32.f32 "
                        "{%0,%1,%2,%3}, {%4,%5,%6,%7}, {%8,%9}, {%0,%1,%2,%3};"
                        : "+f"(acc[mt][nt][0]), "+f"(acc[mt][nt][1]),
                          "+f"(acc[mt][nt][2]), "+f"(acc[mt][nt][3])
                        : "r"(a[mt][0]), "r"(a[mt][1]), "r"(a[mt][2]), "r"(a[mt][3]),
                          "r"(bfr[nt][0]), "r"(bfr[nt][1]));
        }
        __syncthreads();
    }

    /* epilogue: +b1 (first half only), pack half2, store */
#pragma unroll
    for (int mt = 0; mt < 2; mt++) {
        int r = row0 + wm * 32 + mt * 16 + gid;
#pragma unroll
        for (int nt = 0; nt < 4; nt++) {
            int col = n0 + wn * 32 + nt * 8 + tig * 2;
            float bx = 0.f, by = 0.f;
            if (!second) { float2 bv = *(const float2*)(b1 + col); bx = bv.x; by = bv.y; }
            g_sh[r * H2 + (col >> 1)]       = pack_h2(acc[mt][nt][0] + bx, acc[mt][nt][1] + by);
            g_sh[(r + 8) * H2 + (col >> 1)] = pack_h2(acc[mt][nt][2] + bx, acc[mt][nt][3] + by);
        }
    }
}

/* ===== fused score: round-2 inner loop, 16i x 32j tiles, 512 CTAs ===== */
__global__ void __launch_bounds__(128) score_kernel(const float* __restrict__ W2)
{
    __shared__ unsigned s1s[16 * 128];   /* [i][hh] half2                  */
    __shared__ unsigned s2s[32 * 129];   /* [j][hh] pad 129: conflict-free */
    __shared__ float2   w2s[128];
    __shared__ float    colbuf[4][32];

    const int jh = blockIdx.x, ih = blockIdx.y, b = blockIdx.z;
    const int tid = threadIdx.x, lane = tid & 31, w = tid >> 5;

    w2s[tid] = *(const float2*)(W2 + tid * 2);

    /* s1: 16 rows x 128 half2 = 512 uint4 (4/thread) */
    const unsigned* s1g = g_sh + (b * NATOMS + ih * 16) * H2;
#pragma unroll
    for (int l = 0; l < 4; l++) {
        int f = tid + l * 128;
        *(uint4*)&s1s[f * 4] = *(const uint4*)(s1g + f * 4);
    }
    /* s2: 32 rows x 128 half2 = 1024 uint4 (8/thread), pad-129 scalar stores */
    const unsigned* s2g = g_sh + (BATCH * NATOMS + b * NATOMS + jh * 32) * H2;
#pragma unroll
    for (int l = 0; l < 8; l++) {
        int f = tid + l * 128;
        int j = f >> 5, q = f & 31;
        uint4 v = *(const uint4*)(s2g + f * 4);
        unsigned* d = &s2s[j * 129 + q * 4];
        d[0] = v.x; d[1] = v.y; d[2] = v.z; d[3] = v.w;
    }
    __syncthreads();

    /* warp w owns i rows [w*4, w*4+4), lane = local j */
    const unsigned* s2row = &s2s[lane * 129];
    float accA[4], accB[4];
#pragma unroll
    for (int ii = 0; ii < 4; ii++) { accA[ii] = 0.f; accB[ii] = 0.f; }

#pragma unroll 4
    for (int hh = 0; hh < 128; hh++) {
        float2 wv = w2s[hh];           /* LDS.64 broadcast */
        unsigned b2 = s2row[hh];       /* conflict-free    */
#pragma unroll
        for (int ii = 0; ii < 4; ii++) {
            unsigned a2 = s1s[(w * 4 + ii) * 128 + hh];   /* broadcast */
            unsigned t = tanh2u(hadd2u(a2, b2));
            float2 tf = __half22float2(u2h(t));
            accA[ii] = fmaf(wv.x, tf.x, accA[ii]);
            accB[ii] = fmaf(wv.y, tf.y, accB[ii]);
        }
    }

    float colacc = 0.f;
#pragma unroll
    for (int ii = 0; ii < 4; ii++) {
        float e = __expf(accA[ii] + accB[ii]);   /* bounded: no max pass */
        colacc += e;
        float rs = e;
#pragma unroll
        for (int o = 16; o > 0; o >>= 1)
            rs += __shfl_xor_sync(0xffffffffu, rs, o);
        if (lane == 0)
            g_rp[(b * NATOMS + ih * 16 + w * 4 + ii) * 2 + jh] = rs;
    }
    colbuf[w][lane] = colacc;
    __syncthreads();
    if (tid < 32) {
        float s = (colbuf[0][tid] + colbuf[1][tid]) +
                  (colbuf[2][tid] + colbuf[3][tid]);
        g_cp[(b * NATOMS + jh * 32 + tid) * 4 + ih] = s;
    }
}

/* ---------------- normalize ---------------- */
__global__ void __launch_bounds__(64) finalize_kernel(float* __restrict__ out)
{
    int b = blockIdx.x, i = threadIdx.x;
    float r = g_rp[(b * 64 + i) * 2] + g_rp[(b * 64 + i) * 2 + 1];
    const float* cp = &g_cp[(b * 64 + i) * 4];
    float c = (cp[0] + cp[1]) + (cp[2] + cp[3]);
    __shared__ float red[64];
    red[i] = r;
    __syncthreads();
    if (i < 32) {
        float v = red[i] + red[i + 32];
#pragma unroll
        for (int o = 16; o > 0; o >>= 1)
            v += __shfl_xor_sync(0xffffffffu, v, o);
        if (i == 0) red[0] = v;
    }
    __syncthreads();
    float inv = 1.f / red[0];
    out[b * 64 + i] = r * inv;
    out[BATCH * NATOMS + b * 64 + i] = c * inv;
}

extern "C" void kernel_launch(void* const* d_in, const int* in_sizes, int n_in,
                              void* d_out, int out_size)
{
    const float *h1 = nullptr, *h2 = nullptr, *W1 = nullptr,
                *b1 = nullptr, *W2 = nullptr;
    for (int idx = 0; idx < n_in; idx++) {
        int sz = in_sizes[idx];
        if (sz == BATCH * NATOMS * HDIM) {
            if (!h1) h1 = (const float*)d_in[idx];
            else if (!h2) h2 = (const float*)d_in[idx];
        } else if (sz == 2 * HDIM * HDIM) {
            W1 = (const float*)d_in[idx];
        } else if (sz == HDIM) {
            if (!b1) b1 = (const float*)d_in[idx];
            else if (!W2) W2 = (const float*)d_in[idx];
        }
    }
    float* out = (float*)d_out;

    gemm_kernel<<<dim3(NROWS / 64, HDIM / 64), 128>>>(h1, h2, W1, b1);
    score_kernel<<<dim3(2, 4, BATCH), 128>>>(W2);
    finalize_kernel<<<BATCH, 64>>>(out);
}

// round 6
// speedup vs baseline: 1.0985x; 1.0626x over previous
#include <cuda_runtime.h>
#include <cuda_fp16.h>

#define BATCH   64
#define NATOMS  64
#define HDIM    256
#define NROWS   (2 * BATCH * NATOMS)   /* 8192 */
#define H2      (HDIM / 2)             /* 128 half2 per row */

/* s = [h1@W1[:H]+b1 ; h2@W1[H:]] packed half2 (4 MB) */
__device__ unsigned g_sh[NROWS * H2];
__device__ float g_rp[BATCH * NATOMS * 2];   /* row partials, 2 j-halves */
__device__ float g_cp[BATCH * NATOMS * 2];   /* col partials, 2 i-halves */

__device__ __forceinline__ unsigned pack_h2(float x, float y) {
    __half2 h = __floats2half2_rn(x, y);
    return *reinterpret_cast<unsigned*>(&h);
}
__device__ __forceinline__ unsigned tanh2u(unsigned x) {
    unsigned y; asm("tanh.approx.f16x2 %0, %1;" : "=r"(y) : "r"(x)); return y;
}
__device__ __forceinline__ __half2 u2h(unsigned u) {
    return *reinterpret_cast<__half2*>(&u);
}
__device__ __forceinline__ unsigned hadd2u(unsigned a, unsigned b) {
    __half2 r = __hadd2(u2h(a), u2h(b));
    return *reinterpret_cast<unsigned*>(&r);
}
__device__ __forceinline__ unsigned hfma2u(unsigned a, unsigned b, unsigned c) {
    __half2 r = __hfma2(u2h(a), u2h(b), u2h(c));
    return *reinterpret_cast<unsigned*>(&r);
}
__device__ __forceinline__ void cp_async16(void* smem, const void* gmem) {
    unsigned s = (unsigned)__cvta_generic_to_shared(smem);
    asm volatile("cp.async.cg.shared.global [%0], [%1], 16;" :: "r"(s), "l"(gmem));
}

/* ===== tf32 tensor GEMM: R3-proven config (64x64, 128 thr, 2-stage) ===== */
__global__ void __launch_bounds__(128) gemm_kernel(
    const float* __restrict__ h1, const float* __restrict__ h2,
    const float* __restrict__ W1, const float* __restrict__ b1)
{
    __shared__ float As[2][64 * 36];   /* [row][k], pad 36 -> conflict-free */
    __shared__ float Bs[2][32 * 72];   /* [k][n],   pad 72 -> conflict-free */

    const int row0 = blockIdx.x * 64;
    const int n0   = blockIdx.y * 64;
    const bool second = (row0 >= BATCH * NATOMS);
    const float* A = second ? h2 + (row0 - BATCH * NATOMS) * HDIM
                            : h1 + row0 * HDIM;
    const float* W = W1 + (second ? HDIM * HDIM : 0);

    const int tid = threadIdx.x;
    const int lane = tid & 31, w = tid >> 5;
    const int wm = w >> 1, wn = w & 1;
    const int gid = lane >> 2, tig = lane & 3;

    int ar[4], ac[4], bk[4], bn[4];
#pragma unroll
    for (int l = 0; l < 4; l++) {
        int f = tid + l * 128;
        ar[l] = f >> 3;  ac[l] = f & 7;
        bk[l] = f >> 4;  bn[l] = f & 15;
    }

    float acc[2][4][4];
#pragma unroll
    for (int mt = 0; mt < 2; mt++)
#pragma unroll
        for (int nt = 0; nt < 4; nt++)
#pragma unroll
            for (int q = 0; q < 4; q++) acc[mt][nt][q] = 0.f;

#pragma unroll
    for (int l = 0; l < 4; l++)
        cp_async16(&As[0][ar[l] * 36 + ac[l] * 4], A + ar[l] * HDIM + ac[l] * 4);
#pragma unroll
    for (int l = 0; l < 4; l++)
        cp_async16(&Bs[0][bk[l] * 72 + bn[l] * 4], W + bk[l] * HDIM + n0 + bn[l] * 4);
    asm volatile("cp.async.commit_group;");

    for (int kci = 0; kci < 8; kci++) {
        const int s = kci & 1;
        if (kci + 1 < 8) {
            const int kc = (kci + 1) * 32;
#pragma unroll
            for (int l = 0; l < 4; l++)
                cp_async16(&As[s ^ 1][ar[l] * 36 + ac[l] * 4],
                           A + ar[l] * HDIM + kc + ac[l] * 4);
#pragma unroll
            for (int l = 0; l < 4; l++)
                cp_async16(&Bs[s ^ 1][bk[l] * 72 + bn[l] * 4],
                           W + (kc + bk[l]) * HDIM + n0 + bn[l] * 4);
            asm volatile("cp.async.commit_group;");
            asm volatile("cp.async.wait_group 1;");
        } else {
            asm volatile("cp.async.wait_group 0;");
        }
        __syncthreads();

        const unsigned* Au = (const unsigned*)As[s];
        const unsigned* Bu = (const unsigned*)Bs[s];
#pragma unroll
        for (int ks = 0; ks < 4; ks++) {
            unsigned a[2][4], bfr[4][2];
#pragma unroll
            for (int mt = 0; mt < 2; mt++) {
                int r = wm * 32 + mt * 16 + gid;
                int kk = ks * 8 + tig;
                a[mt][0] = Au[r * 36 + kk];
                a[mt][1] = Au[(r + 8) * 36 + kk];
                a[mt][2] = Au[r * 36 + kk + 4];
                a[mt][3] = Au[(r + 8) * 36 + kk + 4];
            }
#pragma unroll
            for (int nt = 0; nt < 4; nt++) {
                int c = wn * 32 + nt * 8 + gid;
                bfr[nt][0] = Bu[(ks * 8 + tig) * 72 + c];
                bfr[nt][1] = Bu[(ks * 8 + tig + 4) * 72 + c];
            }
#pragma unroll
            for (int mt = 0; mt < 2; mt++)
#pragma unroll
                for (int nt = 0; nt < 4; nt++)
                    asm volatile(
                        "mma.sync.aligned.m16n8k8.row.col.f32.tf32.tf32.f32 "
                        "{%0,%1,%2,%3}, {%4,%5,%6,%7}, {%8,%9}, {%0,%1,%2,%3};"
                        : "+f"(acc[mt][nt][0]), "+f"(acc[mt][nt][1]),
                          "+f"(acc[mt][nt][2]), "+f"(acc[mt][nt][3])
                        : "r"(a[mt][0]), "r"(a[mt][1]), "r"(a[mt][2]), "r"(a[mt][3]),
                          "r"(bfr[nt][0]), "r"(bfr[nt][1]));
        }
        __syncthreads();
    }

#pragma unroll
    for (int mt = 0; mt < 2; mt++) {
        int r = row0 + wm * 32 + mt * 16 + gid;
#pragma unroll
        for (int nt = 0; nt < 4; nt++) {
            int col = n0 + wn * 32 + nt * 8 + tig * 2;
            float bx = 0.f, by = 0.f;
            if (!second) { float2 bv = *(const float2*)(b1 + col); bx = bv.x; by = bv.y; }
            g_sh[r * H2 + (col >> 1)]       = pack_h2(acc[mt][nt][0] + bx, acc[mt][nt][1] + by);
            g_sh[(r + 8) * H2 + (col >> 1)] = pack_h2(acc[mt][nt][2] + bx, acc[mt][nt][3] + by);
        }
    }
}

/* ===== score: R2 structure + f16x2 chunked accumulation (HFMA2) ===== */
__global__ void __launch_bounds__(256) score_kernel(const float* __restrict__ W2)
{
    __shared__ unsigned s1s[32 * 128];   /* [i][hh] half2                  */
    __shared__ unsigned s2s[32 * 129];   /* [j][hh] pad 129: conflict-free */
    __shared__ unsigned w2s[128];        /* packed f16x2 w2 pairs          */
    __shared__ float    colbuf[8][32];

    const int jh = blockIdx.x, ih = blockIdx.y, b = blockIdx.z;
    const int tid = threadIdx.x, lane = tid & 31, w = tid >> 5;

    if (tid < 128) {
        float2 v = *(const float2*)(W2 + tid * 2);
        w2s[tid] = pack_h2(v.x, v.y);
    }

    /* s1: 32 rows x 128 half2 = 1024 uint4 (4/thread), linear */
    const unsigned* s1g = g_sh + (b * NATOMS + ih * 32) * H2;
#pragma unroll
    for (int l = 0; l < 4; l++) {
        int f = tid + l * 256;
        *(uint4*)&s1s[f * 4] = *(const uint4*)(s1g + f * 4);
    }
    /* s2: pad-129 rows, scalar stores */
    const unsigned* s2g = g_sh + (BATCH * NATOMS + b * NATOMS + jh * 32) * H2;
#pragma unroll
    for (int l = 0; l < 4; l++) {
        int f = tid + l * 256;
        int j = f >> 5, q = f & 31;
        uint4 v = *(const uint4*)(s2g + f * 4);
        unsigned* d = &s2s[j * 129 + q * 4];
        d[0] = v.x; d[1] = v.y; d[2] = v.z; d[3] = v.w;
    }
    __syncthreads();

    /* warp w owns i rows [w*4, w*4+4), lane = local j */
    const unsigned* s2row = &s2s[lane * 129];
    float facc[4];
#pragma unroll
    for (int ii = 0; ii < 4; ii++) facc[ii] = 0.f;

#pragma unroll 1
    for (int ch = 0; ch < 8; ch++) {
        unsigned hacc[4];
#pragma unroll
        for (int ii = 0; ii < 4; ii++) hacc[ii] = 0u;
#pragma unroll
        for (int t = 0; t < 16; t++) {
            int hh = ch * 16 + t;
            unsigned wp = w2s[hh];         /* broadcast     */
            unsigned b2 = s2row[hh];       /* conflict-free */
#pragma unroll
            for (int ii = 0; ii < 4; ii++) {
                unsigned a2 = s1s[(w * 4 + ii) * 128 + hh];   /* broadcast */
                unsigned th = tanh2u(hadd2u(a2, b2));
                hacc[ii] = hfma2u(th, wp, hacc[ii]);
            }
        }
#pragma unroll
        for (int ii = 0; ii < 4; ii++) {
            float2 f = __half22float2(u2h(hacc[ii]));
            facc[ii] += f.x + f.y;
        }
    }

    float colacc = 0.f;
#pragma unroll
    for (int ii = 0; ii < 4; ii++) {
        float e = __expf(facc[ii]);        /* bounded scores: no max pass */
        colacc += e;
        float rs = e;
#pragma unroll
        for (int o = 16; o > 0; o >>= 1)
            rs += __shfl_xor_sync(0xffffffffu, rs, o);
        if (lane == 0)
            g_rp[(b * NATOMS + ih * 32 + w * 4 + ii) * 2 + jh] = rs;
    }
    colbuf[w][lane] = colacc;
    __syncthreads();
    if (tid < 32) {
        float s = ((colbuf[0][tid] + colbuf[1][tid]) +
                   (colbuf[2][tid] + colbuf[3][tid])) +
                  ((colbuf[4][tid] + colbuf[5][tid]) +
                   (colbuf[6][tid] + colbuf[7][tid]));
        g_cp[(b * NATOMS + jh * 32 + tid) * 2 + ih] = s;
    }
}

/* ---------------- normalize ---------------- */
__global__ void __launch_bounds__(64) finalize_kernel(float* __restrict__ out)
{
    int b = blockIdx.x, i = threadIdx.x;
    float r = g_rp[(b * 64 + i) * 2] + g_rp[(b * 64 + i) * 2 + 1];
    float c = g_cp[(b * 64 + i) * 2] + g_cp[(b * 64 + i) * 2 + 1];
    __shared__ float red[64];
    red[i] = r;
    __syncthreads();
    if (i < 32) {
        float v = red[i] + red[i + 32];
#pragma unroll
        for (int o = 16; o > 0; o >>= 1)
            v += __shfl_xor_sync(0xffffffffu, v, o);
        if (i == 0) red[0] = v;
    }
    __syncthreads();
    float inv = 1.f / red[0];
    out[b * 64 + i] = r * inv;
    out[BATCH * NATOMS + b * 64 + i] = c * inv;
}

extern "C" void kernel_launch(void* const* d_in, const int* in_sizes, int n_in,
                              void* d_out, int out_size)
{
    const float *h1 = nullptr, *h2 = nullptr, *W1 = nullptr,
                *b1 = nullptr, *W2 = nullptr;
    for (int idx = 0; idx < n_in; idx++) {
        int sz = in_sizes[idx];
        if (sz == BATCH * NATOMS * HDIM) {
            if (!h1) h1 = (const float*)d_in[idx];
            else if (!h2) h2 = (const float*)d_in[idx];
        } else if (sz == 2 * HDIM * HDIM) {
            W1 = (const float*)d_in[idx];
        } else if (sz == HDIM) {
            if (!b1) b1 = (const float*)d_in[idx];
            else if (!W2) W2 = (const float*)d_in[idx];
        }
    }
    float* out = (float*)d_out;

    gemm_kernel<<<dim3(NROWS / 64, HDIM / 64), 128>>>(h1, h2, W1, b1);
    score_kernel<<<dim3(2, 2, BATCH), 256>>>(W2);
    finalize_kernel<<<BATCH, 64>>>(out);
}